// round 7
// baseline (speedup 1.0000x reference)
#include <cuda_runtime.h>
#include <cuda_fp16.h>

// DiffeomorphicTransform: scaling-and-squaring, 7 steps.
// R6: 2 adjacent x-voxels per thread (halved structured-instruction count,
//     doubled gather MLP), planar fp32 carry + packed fp16 gather mirror.

#define DD 128
#define HH 160
#define WW 128
#define NVOX (DD * HH * WW)          // 2,621,440
#define NELEM (3 * NVOX)
#define NPAIR (NVOX / 2)

// Ping-pong scratch (no cudaMalloc allowed).
__device__ float g_fA[NELEM];        // planar fp32 carry
__device__ float g_fB[NELEM];
__device__ uint2 g_hA[NVOX];         // fp16 mirror: half2(x,y), half2(z,0)
__device__ uint2 g_hB[NVOX];

__device__ __forceinline__ uint2 pack_h(float x, float y, float z) {
    __half2 xy = __floats2half2_rn(x, y);
    __half2 z0 = __floats2half2_rn(z, 0.0f);
    uint2 r;
    r.x = *reinterpret_cast<unsigned int*>(&xy);
    r.y = *reinterpret_cast<unsigned int*>(&z0);
    return r;
}

__device__ __forceinline__ float3 unpack_h(uint2 raw) {
    __half2 xy = *reinterpret_cast<__half2*>(&raw.x);
    __half2 z0 = *reinterpret_cast<__half2*>(&raw.y);
    float2 fxy = __half22float2(xy);
    return make_float3(fxy.x, fxy.y, __low2float(z0));
}

// Full trilinear sample+add for one voxel. Returns self + interp(mirror).
__device__ __forceinline__ float3 sample_one(
    const uint2* __restrict__ hin,
    int x, int y, int z,
    float fx, float fy, float fz,
    float sx, float sy, float sz)
{
    float ix = fmaf(fx, sx, (float)x);
    float iy = fmaf(fy, sy, (float)y);
    float iz = fmaf(fz, sz, (float)z);
    ix = fminf(fmaxf(ix, 0.0f), (float)(WW - 1));
    iy = fminf(fmaxf(iy, 0.0f), (float)(HH - 1));
    iz = fminf(fmaxf(iz, 0.0f), (float)(DD - 1));

    const float x0f = floorf(ix), y0f = floorf(iy), z0f = floorf(iz);
    const float wx = ix - x0f, wy = iy - y0f, wz = iz - z0f;
    const int x0 = (int)x0f, y0 = (int)y0f, z0 = (int)z0f;
    const int x1 = min(x0 + 1, WW - 1);
    const int y1 = min(y0 + 1, HH - 1);
    const int z1 = min(z0 + 1, DD - 1);

    const int b00 = (z0 * HH + y0) * WW;
    const int b01 = (z0 * HH + y1) * WW;
    const int b10 = (z1 * HH + y0) * WW;
    const int b11 = (z1 * HH + y1) * WW;

    const float3 c000 = unpack_h(__ldg(&hin[b00 + x0]));
    const float3 c001 = unpack_h(__ldg(&hin[b00 + x1]));
    const float3 c010 = unpack_h(__ldg(&hin[b01 + x0]));
    const float3 c011 = unpack_h(__ldg(&hin[b01 + x1]));
    const float3 c100 = unpack_h(__ldg(&hin[b10 + x0]));
    const float3 c101 = unpack_h(__ldg(&hin[b10 + x1]));
    const float3 c110 = unpack_h(__ldg(&hin[b11 + x0]));
    const float3 c111 = unpack_h(__ldg(&hin[b11 + x1]));

    const float owx = 1.0f - wx, owy = 1.0f - wy, owz = 1.0f - wz;
    const float w00 = owz * owy, w01 = owz * wy, w10 = wz * owy, w11 = wz * wy;
    const float w000 = w00 * owx, w001 = w00 * wx;
    const float w010 = w01 * owx, w011 = w01 * wx;
    const float w100 = w10 * owx, w101 = w10 * wx;
    const float w110 = w11 * owx, w111 = w11 * wx;

    float rx = fx, ry = fy, rz = fz;
    rx = fmaf(w000, c000.x, rx); ry = fmaf(w000, c000.y, ry); rz = fmaf(w000, c000.z, rz);
    rx = fmaf(w001, c001.x, rx); ry = fmaf(w001, c001.y, ry); rz = fmaf(w001, c001.z, rz);
    rx = fmaf(w010, c010.x, rx); ry = fmaf(w010, c010.y, ry); rz = fmaf(w010, c010.z, rz);
    rx = fmaf(w011, c011.x, rx); ry = fmaf(w011, c011.y, ry); rz = fmaf(w011, c011.z, rz);
    rx = fmaf(w100, c100.x, rx); ry = fmaf(w100, c100.y, ry); rz = fmaf(w100, c100.z, rz);
    rx = fmaf(w101, c101.x, rx); ry = fmaf(w101, c101.y, ry); rz = fmaf(w101, c101.z, rz);
    rx = fmaf(w110, c110.x, rx); ry = fmaf(w110, c110.y, ry); rz = fmaf(w110, c110.z, rz);
    rx = fmaf(w111, c111.x, rx); ry = fmaf(w111, c111.y, ry); rz = fmaf(w111, c111.z, rz);
    return make_float3(rx, ry, rz);
}

// planar velocity -> planar fp32 (scaled 1/128) + fp16 mirror; 2 voxels/thread
__global__ void __launch_bounds__(256) convert_kernel(
    const float* __restrict__ vel, float* __restrict__ out, uint2* __restrict__ outh)
{
    int t = blockIdx.x * blockDim.x + threadIdx.x;
    if (t >= NPAIR) return;
    const int v = t * 2;
    const float s = 1.0f / 128.0f;
    float2 vx = *reinterpret_cast<const float2*>(&vel[v]);
    float2 vy = *reinterpret_cast<const float2*>(&vel[NVOX + v]);
    float2 vz = *reinterpret_cast<const float2*>(&vel[2 * NVOX + v]);
    vx.x *= s; vx.y *= s; vy.x *= s; vy.y *= s; vz.x *= s; vz.y *= s;
    *reinterpret_cast<float2*>(&out[v])            = vx;
    *reinterpret_cast<float2*>(&out[NVOX + v])     = vy;
    *reinterpret_cast<float2*>(&out[2 * NVOX + v]) = vz;
    uint2 hA = pack_h(vx.x, vy.x, vz.x);
    uint2 hB = pack_h(vx.y, vy.y, vz.y);
    uint4 rec; rec.x = hA.x; rec.y = hA.y; rec.z = hB.x; rec.w = hB.y;
    *reinterpret_cast<uint4*>(&outh[v]) = rec;
}

template <bool LAST>
__global__ void __launch_bounds__(256, 4) step_kernel(
    const float* __restrict__ fin,     // planar fp32 carry
    const uint2* __restrict__ hin,     // fp16 mirror (gather source)
    const float* __restrict__ rfp,
    float* __restrict__ fout,          // planar fp32 (dst buffer or d_out)
    uint2* __restrict__ houth)         // fp16 mirror out (unused on last)
{
    int t = blockIdx.x * blockDim.x + threadIdx.x;
    if (t >= NPAIR) return;
    const int v = t * 2;

    const float rf = __ldg(rfp);
    const float sx = rf * 0.5f * (float)(WW - 1);
    const float sy = rf * 0.5f * (float)(HH - 1);
    const float sz = rf * 0.5f * (float)(DD - 1);

    // voxel coords (W=128 power of two); pair shares y,z; x even
    const int x = v & (WW - 1);
    const int rest = v >> 7;
    const int y = rest % HH;
    const int z = rest / HH;

    const float2 fx2 = *reinterpret_cast<const float2*>(&fin[v]);
    const float2 fy2 = *reinterpret_cast<const float2*>(&fin[NVOX + v]);
    const float2 fz2 = *reinterpret_cast<const float2*>(&fin[2 * NVOX + v]);

    const float3 rA = sample_one(hin, x,     y, z, fx2.x, fy2.x, fz2.x, sx, sy, sz);
    const float3 rB = sample_one(hin, x + 1, y, z, fx2.y, fy2.y, fz2.y, sx, sy, sz);

    *reinterpret_cast<float2*>(&fout[v])            = make_float2(rA.x, rB.x);
    *reinterpret_cast<float2*>(&fout[NVOX + v])     = make_float2(rA.y, rB.y);
    *reinterpret_cast<float2*>(&fout[2 * NVOX + v]) = make_float2(rA.z, rB.z);

    if (!LAST) {
        uint2 hA = pack_h(rA.x, rA.y, rA.z);
        uint2 hB = pack_h(rB.x, rB.y, rB.z);
        uint4 rec; rec.x = hA.x; rec.y = hA.y; rec.z = hB.x; rec.w = hB.y;
        *reinterpret_cast<uint4*>(&houth[v]) = rec;
    }
}

extern "C" void kernel_launch(void* const* d_in, const int* in_sizes, int n_in,
                              void* d_out, int out_size) {
    (void)in_sizes; (void)n_in; (void)out_size;
    const float* velocity = (const float*)d_in[0];
    const float* rf       = (const float*)d_in[2];
    float* out            = (float*)d_out;

    float *fA, *fB;
    uint2 *hA, *hB;
    cudaGetSymbolAddress((void**)&fA, g_fA);
    cudaGetSymbolAddress((void**)&fB, g_fB);
    cudaGetSymbolAddress((void**)&hA, g_hA);
    cudaGetSymbolAddress((void**)&hB, g_hB);

    const int T = 256;
    const int G = (NPAIR + T - 1) / T;

    convert_kernel<<<G, T>>>(velocity, fA, hA);

    float* src = fA;  uint2* hsrc = hA;
    float* dst = fB;  uint2* hdst = hB;
    for (int it = 0; it < 6; it++) {
        step_kernel<false><<<G, T>>>(src, hsrc, rf, dst, hdst);
        float* t1 = src; src = dst; dst = t1;
        uint2* t2 = hsrc; hsrc = hdst; hdst = t2;
    }
    step_kernel<true><<<G, T>>>(src, hsrc, rf, out, nullptr);
}